// round 13
// baseline (speedup 1.0000x reference)
#include <cuda_runtime.h>
#include <cuda_bf16.h>
#include <cuda_fp16.h>
#include <math.h>
#include <stdint.h>

// Problem constants (fixed by the dataset)
#define NN 50000
#define EE 800000
#define INC 128
#define D1 256     // HID*HEADS
#define EMB 128

// ---------------- scratch (device globals; no allocation allowed) ------------
__device__ float g_q1[NN * D1];
__device__ float g_h [NN * D1];   // layer1 skip (from GEMM)
__device__ float g_q2[NN * EMB];
__device__ float g_o2[NN * EMB];  // layer2 skip + attention out

// fp16 k/v (gather-bandwidth halving)
__device__ __half g_k1h[NN * D1];
__device__ __half g_v1h[NN * D1];
__device__ __half g_k2h[NN * EMB];
__device__ __half g_v2h[NN * EMB];

// fp16 activations for GEMM A operand
__device__ __half g_xf[NN * INC];
__device__ __half g_hf[NN * D1];
// transposed fp16 hi/lo weights: layer1 at [0,131072), layer2 at [131072,262144).
// Layout: Wt[n][k] row-major.
__device__ __half g_wh[262144];
__device__ __half g_wl[262144];

__device__ int g_deg   [NN];
__device__ int g_cursor[NN];
__device__ int g_incl  [NN];
__device__ int g_offs  [NN + 1];
__device__ int g_part  [128];
__device__ int g_cbase [128];
__device__ int g_srcs  [EE];
__device__ int g_is64;            // 1 if edge_index is int64, 0 if int32

// fp32 output selector (sels 0,3,4,7)
__device__ __forceinline__ float* buf_f32(int sel) {
    switch (sel) {
        case 0: return g_q1;
        case 3: return g_h;
        case 4: return g_q2;
        default: return g_o2;
    }
}
// fp16 output selector (sels 1,2,5,6)
__device__ __forceinline__ __half* buf_f16(int sel) {
    switch (sel) {
        case 1: return g_k1h;
        case 2: return g_v1h;
        case 5: return g_k2h;
        default: return g_v2h;
    }
}

__device__ __forceinline__ int edge_val(const void* ei, long long idx) {
    if (g_is64) return (int)((const long long*)ei)[idx];
    return ((const int*)ei)[idx];
}

__device__ __forceinline__ uint32_t smem_u32(const void* p) {
    uint32_t a;
    asm("{ .reg .u64 t; cvta.to.shared.u64 t, %1; cvt.u32.u64 %0, t; }"
        : "=r"(a) : "l"(p));
    return a;
}

__device__ __forceinline__ void ldsm4(uint32_t* r, uint32_t addr) {
    asm volatile("ldmatrix.sync.aligned.m8n8.x4.shared.b16 {%0,%1,%2,%3}, [%4];"
                 : "=r"(r[0]), "=r"(r[1]), "=r"(r[2]), "=r"(r[3]) : "r"(addr));
}

// mma m16n8k16 fp16 -> fp32 accumulate
__device__ __forceinline__ void mma_f16(float* d, const uint32_t* a,
                                        uint32_t b0, uint32_t b1) {
    asm volatile(
        "mma.sync.aligned.m16n8k16.row.col.f32.f16.f16.f32 "
        "{%0,%1,%2,%3}, {%4,%5,%6,%7}, {%8,%9}, {%0,%1,%2,%3};"
        : "+f"(d[0]), "+f"(d[1]), "+f"(d[2]), "+f"(d[3])
        : "r"(a[0]), "r"(a[1]), "r"(a[2]), "r"(a[3]), "r"(b0), "r"(b1));
}

__device__ __forceinline__ void cpasync16(uint32_t dst, const void* src, int sz) {
    asm volatile("cp.async.cg.shared.global [%0], [%1], 16, %2;"
                 :: "r"(dst), "l"(src), "r"(sz) : "memory");
}

// ---------------- init (+ edge dtype detection) ------------------------------
__global__ void init_kernel(const void* ei, float* out, int n) {
    int i = blockIdx.x * blockDim.x + threadIdx.x;
    if (i < n) { g_deg[i] = 0; g_cursor[i] = 0; }
    if (i < EMB) out[i] = 0.0f;
    if (i == 0) {
        g_offs[0] = 0;
        const long long* p = (const long long*)ei;
        int ok = 1;
        for (int j = 0; j < 32; ++j) {
            long long v = p[j];
            if (v < 0 || v >= n) ok = 0;
        }
        g_is64 = ok;
    }
}

// ---------------- CSR build -------------------------------------------------
__global__ void hist_kernel(const void* __restrict__ ei, int e, int n) {
    int idx = blockIdx.x * blockDim.x + threadIdx.x;
    if (idx < e) {
        int d = edge_val(ei, (long long)e + idx);
        if (d >= 0 && d < n) atomicAdd(&g_deg[d], 1);
    }
}

__global__ void scanA_kernel(int n) {
    __shared__ int s[512];
    int t = threadIdx.x;
    int i = blockIdx.x * 512 + t;
    int v = (i < n) ? g_deg[i] : 0;
    s[t] = v;
    __syncthreads();
    #pragma unroll
    for (int off = 1; off < 512; off <<= 1) {
        int add = (t >= off) ? s[t - off] : 0;
        __syncthreads();
        s[t] += add;
        __syncthreads();
    }
    if (i < n) g_incl[i] = s[t];
    if (t == 511) g_part[blockIdx.x] = s[511];
}

__global__ void scanB_kernel(int nchunks) {
    __shared__ int s[128];
    int t = threadIdx.x;
    int v = (t < nchunks) ? g_part[t] : 0;
    s[t] = v;
    __syncthreads();
    #pragma unroll
    for (int off = 1; off < 128; off <<= 1) {
        int add = (t >= off) ? s[t - off] : 0;
        __syncthreads();
        s[t] += add;
        __syncthreads();
    }
    if (t < nchunks) g_cbase[t] = s[t] - v;   // exclusive
}

__global__ void scanC_kernel(int n) {
    int i = blockIdx.x * blockDim.x + threadIdx.x;
    if (i < n) g_offs[i + 1] = g_cbase[i >> 9] + g_incl[i];
}

__global__ void scatter_kernel(const void* __restrict__ ei, int e, int n) {
    int idx = blockIdx.x * blockDim.x + threadIdx.x;
    if (idx < e) {
        int d = edge_val(ei, (long long)e + idx);
        int s = edge_val(ei, idx);
        if (d >= 0 && d < n && s >= 0 && s < n) {
            int pos = g_offs[d] + atomicAdd(&g_cursor[d], 1);
            g_srcs[pos] = s;
        }
    }
}

// ---------------- conversion passes -------------------------------------------
__global__ void xconv_kernel(const float* __restrict__ x, int total) {
    int i = blockIdx.x * blockDim.x + threadIdx.x;
    if (i < total) g_xf[i] = __float2half_rn(x[i]);
}

// transpose + fp16 hi/lo split of all 8 weight matrices
__global__ void wsplit_kernel(const float* w0, const float* w1, const float* w2, const float* w3,
                              const float* w4, const float* w5, const float* w6, const float* w7) {
    int tid = blockIdx.x * blockDim.x + threadIdx.x;
    if (tid >= 262144) return;
    float v;
    int idx;
    if (tid < 131072) {
        int m = tid >> 15, r = tid & 32767;
        int n = r >> 7, k = r & 127;
        const float* W = (m == 0) ? w0 : (m == 1) ? w1 : (m == 2) ? w2 : w3;
        v = W[k * 256 + n];
        idx = m * 32768 + n * 128 + k;
    } else {
        int e = tid - 131072;
        int m = e >> 15, r = e & 32767;
        int n = r >> 8, k = r & 255;
        const float* W = (m == 0) ? w4 : (m == 1) ? w5 : (m == 2) ? w6 : w7;
        v = W[k * 128 + n];
        idx = 131072 + m * 32768 + n * 256 + k;
    }
    __half hi = __float2half_rn(v);
    g_wh[idx] = hi;
    g_wl[idx] = __float2half_rn(v - __half2float(hi));
}

// ---------------- mma.sync fp16 GEMM, 2-term, 2-stage cp.async ----------------
// C = A(fp16) @ (Wh + Wl)^T + bias. A[M,K], Wt[N,K]. fp32 accum.
#define BK 32
#define LDT 40
#define TILE_ELEMS (128 * LDT)
#define STAGE_ELEMS (3 * TILE_ELEMS)            // A, Bh, Bl
#define GEMM_SMEM_BYTES (2 * STAGE_ELEMS * 2)   // 61440 B

__global__ __launch_bounds__(256, 2)
void mma_gemm_kernel(const float* __restrict__ b0, const float* __restrict__ b1,
                     const float* __restrict__ b2, const float* __restrict__ b3,
                     int M, int K, int ntiles, int wt_base, int layer, int out_base)
{
    extern __shared__ __align__(16) __half sm[];

    int tid = threadIdx.x, wid = tid >> 5, lane = tid & 31;
    int mat = blockIdx.x / ntiles, nt0 = blockIdx.x % ntiles;
    int m0 = blockIdx.y * 128;
    int n0 = nt0 * 128;
    int Ntot = ntiles * 128;

    const __half* Af = layer ? g_hf : g_xf;
    const __half* Bh = g_wh + wt_base + mat * 32768;
    const __half* Bl = g_wl + wt_base + mat * 32768;
    const float* bias = (mat == 0) ? b0 : (mat == 1) ? b1 : (mat == 2) ? b2 : b3;
    int osel = out_base + mat;
    bool is_half = (osel == 1 || osel == 2 || osel == 5 || osel == 6);

    int warp_m = wid >> 1;
    int warp_n = wid & 1;

    float acc[2][8][4];
    #pragma unroll
    for (int i = 0; i < 2; ++i)
        #pragma unroll
        for (int j = 0; j < 8; ++j)
            #pragma unroll
            for (int q = 0; q < 4; ++q) acc[i][j][q] = 0.0f;

    uint32_t smu = smem_u32(sm);
    int nchunks = K / BK;

    // 1536 16B-chunks per stage: t=0 A, t=1 Bh, t=2 Bl
    auto issue = [&](int kc) {
        int kb = kc * BK;
        uint32_t sbase = smu + (uint32_t)(kc & 1) * (STAGE_ELEMS * 2);
        #pragma unroll
        for (int it = 0; it < 6; ++it) {
            int i = tid + it * 256;
            int t = i >> 9, w = i & 511;
            int row = w >> 2, c8 = (w & 3) * 8;
            uint32_t dst = sbase + (uint32_t)(t * TILE_ELEMS + row * LDT + c8) * 2;
            if (t == 0) {
                int r = m0 + row;
                const void* sp = (r < M) ? (const void*)(Af + (size_t)r * K + kb + c8)
                                         : (const void*)Af;
                cpasync16(dst, sp, (r < M) ? 16 : 0);
            } else {
                const __half* Bp = (t == 1) ? Bh : Bl;
                cpasync16(dst, Bp + (size_t)(n0 + row) * K + kb + c8, 16);
            }
        }
        asm volatile("cp.async.commit_group;" ::: "memory");
    };

    uint32_t a_row = warp_m * 32 + (lane & 15);
    uint32_t a_koff = (lane >> 4) * 8;
    uint32_t b_nrow = warp_n * 64 + (lane & 7) + ((lane >> 3) & 1) * 8;
    uint32_t b_koff = (lane >> 4) * 8;

    issue(0);

    for (int kc = 0; kc < nchunks; ++kc) {
        if (kc + 1 < nchunks) {
            issue(kc + 1);
            asm volatile("cp.async.wait_group 1;" ::: "memory");
        } else {
            asm volatile("cp.async.wait_group 0;" ::: "memory");
        }
        __syncthreads();

        uint32_t sbase = smu + (uint32_t)(kc & 1) * (STAGE_ELEMS * 2);
        uint32_t sA_u  = sbase;
        uint32_t sBh_u = sbase + TILE_ELEMS * 2;
        uint32_t sBl_u = sbase + 2 * TILE_ELEMS * 2;

        #pragma unroll
        for (int ks = 0; ks < BK / 16; ++ks) {
            uint32_t aF[2][4], bH[4][4], bL[4][4];
            #pragma unroll
            for (int mt = 0; mt < 2; ++mt) {
                uint32_t off = ((a_row + mt * 16) * LDT + ks * 16 + a_koff) * 2;
                ldsm4(aF[mt], sA_u + off);
            }
            #pragma unroll
            for (int nb = 0; nb < 4; ++nb) {
                uint32_t off = ((b_nrow + nb * 16) * LDT + ks * 16 + b_koff) * 2;
                ldsm4(bH[nb], sBh_u + off);
                ldsm4(bL[nb], sBl_u + off);
            }
            #pragma unroll
            for (int mt = 0; mt < 2; ++mt) {
                #pragma unroll
                for (int j = 0; j < 8; ++j) {
                    int nb = j >> 1, par = j & 1;
                    mma_f16(acc[mt][j], aF[mt], bH[nb][par], bH[nb][par + 2]);
                    mma_f16(acc[mt][j], aF[mt], bL[nb][par], bL[nb][par + 2]);
                }
            }
        }
        __syncthreads();
    }

    if (is_half) {
        __half* Ch = buf_f16(osel);
        #pragma unroll
        for (int mt = 0; mt < 2; ++mt) {
            int r0 = m0 + warp_m * 32 + mt * 16 + (lane >> 2);
            #pragma unroll
            for (int j = 0; j < 8; ++j) {
                int c = n0 + warp_n * 64 + j * 8 + (lane & 3) * 2;
                float2 bv = *(const float2*)(bias + c);
                if (r0 < M) {
                    __half2 o0 = __floats2half2_rn(acc[mt][j][0] + bv.x,
                                                   acc[mt][j][1] + bv.y);
                    *(__half2*)(Ch + (size_t)r0 * Ntot + c) = o0;
                }
                if (r0 + 8 < M) {
                    __half2 o1 = __floats2half2_rn(acc[mt][j][2] + bv.x,
                                                   acc[mt][j][3] + bv.y);
                    *(__half2*)(Ch + (size_t)(r0 + 8) * Ntot + c) = o1;
                }
            }
        }
    } else {
        float* C = buf_f32(osel);
        #pragma unroll
        for (int mt = 0; mt < 2; ++mt) {
            int r0 = m0 + warp_m * 32 + mt * 16 + (lane >> 2);
            #pragma unroll
            for (int j = 0; j < 8; ++j) {
                int c = n0 + warp_n * 64 + j * 8 + (lane & 3) * 2;
                float2 bv = *(const float2*)(bias + c);
                if (r0 < M) {
                    float2 o0 = make_float2(acc[mt][j][0] + bv.x, acc[mt][j][1] + bv.y);
                    *(float2*)(C + (size_t)r0 * Ntot + c) = o0;
                }
                if (r0 + 8 < M) {
                    float2 o1 = make_float2(acc[mt][j][2] + bv.x, acc[mt][j][3] + bv.y);
                    *(float2*)(C + (size_t)(r0 + 8) * Ntot + c) = o1;
                }
            }
        }
    }
}

// unpack 8 halves (uint4) -> 8 floats
__device__ __forceinline__ void h8_to_f8(uint4 u, float* f) {
    union { uint4 u; __half2 h[4]; } c;
    c.u = u;
    #pragma unroll
    for (int j = 0; j < 4; ++j) {
        float2 p = __half22float2(c.h[j]);
        f[2 * j] = p.x;
        f[2 * j + 1] = p.y;
    }
}

// ---------------- attention layer 1 (fused skip+attn+relu+fp16 conv) ---------
__global__ void attn1_kernel(int n)
{
    int node = (blockIdx.x * blockDim.x + threadIdx.x) >> 5;
    int lane = threadIdx.x & 31;
    if (node >= n) return;

    int off = (lane >> 3) * 64 + (lane & 7) * 8;
    const float* qb = g_q1 + (size_t)node * D1 + off;
    float4 q0 = *(const float4*)qb;
    float4 q1 = *(const float4*)(qb + 4);
    float qf[8] = { q0.x, q0.y, q0.z, q0.w, q1.x, q1.y, q1.z, q1.w };

    float m = -1e30f, l = 0.0f;
    float A[8] = { 0.f, 0.f, 0.f, 0.f, 0.f, 0.f, 0.f, 0.f };

    int beg = g_offs[node], end = g_offs[node + 1];
    int p = beg;
    for (; p + 4 <= end; p += 4) {
        uint4 kr[4], vr[4];
        #pragma unroll
        for (int j = 0; j < 4; ++j) {
            int s = g_srcs[p + j];
            kr[j] = *(const uint4*)(g_k1h + (size_t)s * D1 + off);
            vr[j] = *(const uint4*)(g_v1h + (size_t)s * D1 + off);
        }
        float d[4];
        #pragma unroll
        for (int j = 0; j < 4; ++j) {
            float kf[8];
            h8_to_f8(kr[j], kf);
            float t = 0.f;
            #pragma unroll
            for (int q = 0; q < 8; ++q) t += qf[q] * kf[q];
            d[j] = t;
        }
        #pragma unroll
        for (int o = 4; o; o >>= 1)
            #pragma unroll
            for (int j = 0; j < 4; ++j)
                d[j] += __shfl_xor_sync(0xffffffffu, d[j], o);
        #pragma unroll
        for (int j = 0; j < 4; ++j) {
            float logit = d[j] * 0.125f;
            float mn = fmaxf(m, logit);
            float c = __expf(m - mn), pe = __expf(logit - mn);
            l = l * c + pe;
            float vf[8];
            h8_to_f8(vr[j], vf);
            #pragma unroll
            for (int q = 0; q < 8; ++q) A[q] = A[q] * c + pe * vf[q];
            m = mn;
        }
    }
    for (; p < end; ++p) {
        int s = g_srcs[p];
        uint4 kr = *(const uint4*)(g_k1h + (size_t)s * D1 + off);
        uint4 vr = *(const uint4*)(g_v1h + (size_t)s * D1 + off);
        float kf[8];
        h8_to_f8(kr, kf);
        float d0 = 0.f;
        #pragma unroll
        for (int q = 0; q < 8; ++q) d0 += qf[q] * kf[q];
        #pragma unroll
        for (int o = 4; o; o >>= 1) d0 += __shfl_xor_sync(0xffffffffu, d0, o);
        float logit = d0 * 0.125f;
        float mn = fmaxf(m, logit);
        float c = __expf(m - mn), pe = __expf(logit - mn);
        l = l * c + pe;
        float vf[8];
        h8_to_f8(vr, vf);
        #pragma unroll
        for (int q = 0; q < 8; ++q) A[q] = A[q] * c + pe * vf[q];
        m = mn;
    }

    float inv = (l > 0.0f) ? 1.0f / l : 0.0f;
    const float* hb = g_h + (size_t)node * D1 + off;
    float4 h0 = *(const float4*)hb;
    float4 h1 = *(const float4*)(hb + 4);
    float hv[8] = { h0.x, h0.y, h0.z, h0.w, h1.x, h1.y, h1.z, h1.w };

    union { uint4 u; __half2 h[4]; } hu;
    #pragma unroll
    for (int j = 0; j < 4; ++j) {
        float v0 = fmaxf(hv[2 * j]     + A[2 * j]     * inv, 0.0f);
        float v1 = fmaxf(hv[2 * j + 1] + A[2 * j + 1] * inv, 0.0f);
        hu.h[j] = __floats2half2_rn(v0, v1);
    }
    *(uint4*)(g_hf + (size_t)node * D1 + off) = hu.u;
}

// ---------------- attention layer 2: 1 head, d=128, warp per node, unroll 4 --
__global__ void attn2_kernel(int n)
{
    int node = (blockIdx.x * blockDim.x + threadIdx.x) >> 5;
    int lane = threadIdx.x & 31;
    if (node >= n) return;

    int base = node * EMB + 4 * lane;
    float4 qv = *(const float4*)(g_q2 + base);

    float m = -1e30f, l = 0.0f;
    float4 A = make_float4(0.f, 0.f, 0.f, 0.f);
    int beg = g_offs[node], end = g_offs[node + 1];
    const float scale = 0.088388347648318447f;   // 1/sqrt(128)

    int p = beg;
    for (; p + 4 <= end; p += 4) {
        uint2 kr[4], vr[4];
        #pragma unroll
        for (int j = 0; j < 4; ++j) {
            int s = g_srcs[p + j];
            kr[j] = *(const uint2*)(g_k2h + (size_t)s * EMB + 4 * lane);
            vr[j] = *(const uint2*)(g_v2h + (size_t)s * EMB + 4 * lane);
        }
        float d[4];
        #pragma unroll
        for (int j = 0; j < 4; ++j) {
            union { uint2 u; __half2 h[2]; } c;
            c.u = kr[j];
            float2 p0 = __half22float2(c.h[0]);
            float2 p1 = __half22float2(c.h[1]);
            d[j] = qv.x * p0.x + qv.y * p0.y + qv.z * p1.x + qv.w * p1.y;
        }
        #pragma unroll
        for (int o = 16; o; o >>= 1)
            #pragma unroll
            for (int j = 0; j < 4; ++j)
                d[j] += __shfl_xor_sync(0xffffffffu, d[j], o);
        #pragma unroll
        for (int j = 0; j < 4; ++j) {
            float logit = d[j] * scale;
            float mn = fmaxf(m, logit);
            float c = __expf(m - mn), pe = __expf(logit - mn);
            l = l * c + pe;
            union { uint2 u; __half2 h[2]; } cv;
            cv.u = vr[j];
            float2 v0 = __half22float2(cv.h[0]);
            float2 v1 = __half22float2(cv.h[1]);
            A.x = A.x * c + pe * v0.x; A.y = A.y * c + pe * v0.y;
            A.z = A.z * c + pe * v1.x; A.w = A.w * c + pe * v1.y;
            m = mn;
        }
    }
    for (; p < end; ++p) {
        int s = g_srcs[p];
        union { uint2 u; __half2 h[2]; } ck, cv;
        ck.u = *(const uint2*)(g_k2h + (size_t)s * EMB + 4 * lane);
        cv.u = *(const uint2*)(g_v2h + (size_t)s * EMB + 4 * lane);
        float2 p0 = __half22float2(ck.h[0]);
        float2 p1 = __half22float2(ck.h[1]);
        float d0 = qv.x * p0.x + qv.y * p0.y + qv.z * p1.x + qv.w * p1.y;
        #pragma unroll
        for (int o = 16; o; o >>= 1) d0 += __shfl_xor_sync(0xffffffffu, d0, o);
        float logit = d0 * scale;
        float mn = fmaxf(m, logit);
        float c = __expf(m - mn), pe = __expf(logit - mn);
        l = l * c + pe;
        float2 v0 = __half22float2(cv.h[0]);
        float2 v1 = __half22float2(cv.h[1]);
        A.x = A.x * c + pe * v0.x; A.y = A.y * c + pe * v0.y;
        A.z = A.z * c + pe * v1.x; A.w = A.w * c + pe * v1.y;
        m = mn;
    }
    if (l > 0.0f) {
        float inv = 1.0f / l;
        float4 o = *(float4*)(g_o2 + base);
        o.x += A.x * inv; o.y += A.y * inv; o.z += A.z * inv; o.w += A.w * inv;
        *(float4*)(g_o2 + base) = o;
    }
}

// ---------------- final mean over nodes (reads g_o2) -------------------------
__global__ void reduce_mean_kernel(float* __restrict__ out, int n) {
    int col = threadIdx.x;   // 128 threads
    float s = 0.0f;
    for (int r = blockIdx.x; r < n; r += gridDim.x)
        s += g_o2[(size_t)r * EMB + col];
    atomicAdd(&out[col], s * (1.0f / (float)n));
}

// ---------------- launch -----------------------------------------------------
extern "C" void kernel_launch(void* const* d_in, const int* in_sizes, int n_in,
                              void* d_out, int out_size)
{
    const float* x  = (const float*)d_in[0];
    const void*  ei = d_in[1];
    const float *Wq1 = (const float*)d_in[2],  *bq1 = (const float*)d_in[3];
    const float *Wk1 = (const float*)d_in[4],  *bk1 = (const float*)d_in[5];
    const float *Wv1 = (const float*)d_in[6],  *bv1 = (const float*)d_in[7];
    const float *Ws1 = (const float*)d_in[8],  *bs1 = (const float*)d_in[9];
    const float *Wq2 = (const float*)d_in[10], *bq2 = (const float*)d_in[11];
    const float *Wk2 = (const float*)d_in[12], *bk2 = (const float*)d_in[13];
    const float *Wv2 = (const float*)d_in[14], *bv2 = (const float*)d_in[15];
    const float *Ws2 = (const float*)d_in[16], *bs2 = (const float*)d_in[17];
    float* out = (float*)d_out;

    const int n = in_sizes[0] / INC;   // 50000
    const int e = in_sizes[1] / 2;     // 800000

    cudaFuncSetAttribute(mma_gemm_kernel,
                         cudaFuncAttributeMaxDynamicSharedMemorySize, GEMM_SMEM_BYTES);

    // ---- init (+dtype detect) + CSR build (by dst) ----
    {
        int threads = 256;
        init_kernel<<<(n + threads - 1) / threads, threads>>>(ei, out, n);
        hist_kernel<<<(e + threads - 1) / threads, threads>>>(ei, e, n);
        int nchunks = (n + 511) / 512;
        scanA_kernel<<<nchunks, 512>>>(n);
        scanB_kernel<<<1, 128>>>(nchunks);
        scanC_kernel<<<(n + threads - 1) / threads, threads>>>(n);
        scatter_kernel<<<(e + threads - 1) / threads, threads>>>(ei, e, n);
    }

    // ---- input conversions ----
    {
        int totx = n * INC;
        xconv_kernel<<<(totx + 255) / 256, 256>>>(x, totx);
        wsplit_kernel<<<1024, 256>>>(Wq1, Wk1, Wv1, Ws1, Wq2, Wk2, Wv2, Ws2);
    }

    int mtiles = (n + 127) / 128;

    // ---- layer 1 projections (q1 fp32, k1/v1 fp16, h fp32) ----
    {
        dim3 grid(8, mtiles);
        mma_gemm_kernel<<<grid, 256, GEMM_SMEM_BYTES>>>(bq1, bk1, bv1, bs1,
                                                        n, INC, 2, 0, 0, 0);
    }

    // ---- layer 1 attention (fused skip+attn+relu -> g_hf fp16) ----
    {
        int blocks = (n + 7) / 8;
        attn1_kernel<<<blocks, 256>>>(n);
    }

    // ---- layer 2 projections (q2 fp32, k2/v2 fp16, o2 fp32) ----
    {
        dim3 grid(4, mtiles);
        mma_gemm_kernel<<<grid, 256, GEMM_SMEM_BYTES>>>(bq2, bk2, bv2, bs2,
                                                        n, D1, 1, 131072, 1, 4);
    }

    // ---- layer 2 attention (adds into g_o2) ----
    {
        int blocks = (n + 7) / 8;
        attn2_kernel<<<blocks, 256>>>(n);
    }

    // ---- final mean over nodes ----
    reduce_mean_kernel<<<256, EMB>>>(out, n);
}

// round 14
// speedup vs baseline: 1.0015x; 1.0015x over previous
#include <cuda_runtime.h>
#include <cuda_bf16.h>
#include <cuda_fp16.h>
#include <math.h>
#include <stdint.h>

// Problem constants (fixed by the dataset)
#define NN 50000
#define EE 800000
#define INC 128
#define D1 256     // HID*HEADS
#define EMB 128

// ---------------- scratch (device globals; no allocation allowed) ------------
__device__ float g_q1[NN * D1];
__device__ float g_h [NN * D1];   // layer1 skip (from GEMM)
__device__ float g_q2[NN * EMB];
__device__ float g_o2[NN * EMB];  // layer2 skip + attention out

// fp16 k/v (gather-bandwidth halving)
__device__ __half g_k1h[NN * D1];
__device__ __half g_v1h[NN * D1];
__device__ __half g_k2h[NN * EMB];
__device__ __half g_v2h[NN * EMB];

// fp16 activations for GEMM A operand
__device__ __half g_xf[NN * INC];
__device__ __half g_hf[NN * D1];
// transposed fp16 hi/lo weights: layer1 at [0,131072), layer2 at [131072,262144).
// Layout: Wt[n][k] row-major.
__device__ __half g_wh[262144];
__device__ __half g_wl[262144];

__device__ int g_deg   [NN];
__device__ int g_cursor[NN];
__device__ int g_incl  [NN];
__device__ int g_offs  [NN + 1];
__device__ int g_part  [128];
__device__ int g_cbase [128];
__device__ int g_srcs  [EE];
__device__ int g_is64;            // 1 if edge_index is int64, 0 if int32

// fp32 output selector (sels 0,3,4,7)
__device__ __forceinline__ float* buf_f32(int sel) {
    switch (sel) {
        case 0: return g_q1;
        case 3: return g_h;
        case 4: return g_q2;
        default: return g_o2;
    }
}
// fp16 output selector (sels 1,2,5,6)
__device__ __forceinline__ __half* buf_f16(int sel) {
    switch (sel) {
        case 1: return g_k1h;
        case 2: return g_v1h;
        case 5: return g_k2h;
        default: return g_v2h;
    }
}

__device__ __forceinline__ int edge_val(const void* ei, long long idx) {
    if (g_is64) return (int)((const long long*)ei)[idx];
    return ((const int*)ei)[idx];
}

__device__ __forceinline__ uint32_t smem_u32(const void* p) {
    uint32_t a;
    asm("{ .reg .u64 t; cvta.to.shared.u64 t, %1; cvt.u32.u64 %0, t; }"
        : "=r"(a) : "l"(p));
    return a;
}

__device__ __forceinline__ void ldsm4(uint32_t* r, uint32_t addr) {
    asm volatile("ldmatrix.sync.aligned.m8n8.x4.shared.b16 {%0,%1,%2,%3}, [%4];"
                 : "=r"(r[0]), "=r"(r[1]), "=r"(r[2]), "=r"(r[3]) : "r"(addr));
}

// mma m16n8k16 fp16 -> fp32 accumulate
__device__ __forceinline__ void mma_f16(float* d, const uint32_t* a,
                                        uint32_t b0, uint32_t b1) {
    asm volatile(
        "mma.sync.aligned.m16n8k16.row.col.f32.f16.f16.f32 "
        "{%0,%1,%2,%3}, {%4,%5,%6,%7}, {%8,%9}, {%0,%1,%2,%3};"
        : "+f"(d[0]), "+f"(d[1]), "+f"(d[2]), "+f"(d[3])
        : "r"(a[0]), "r"(a[1]), "r"(a[2]), "r"(a[3]), "r"(b0), "r"(b1));
}

__device__ __forceinline__ void cpasync16(uint32_t dst, const void* src, int sz) {
    asm volatile("cp.async.cg.shared.global [%0], [%1], 16, %2;"
                 :: "r"(dst), "l"(src), "r"(sz) : "memory");
}

// ---------------- init (+ edge dtype detection) ------------------------------
__global__ void init_kernel(const void* ei, float* out, int n) {
    int i = blockIdx.x * blockDim.x + threadIdx.x;
    if (i < n) { g_deg[i] = 0; g_cursor[i] = 0; }
    if (i < EMB) out[i] = 0.0f;
    if (i == 0) {
        g_offs[0] = 0;
        const long long* p = (const long long*)ei;
        int ok = 1;
        for (int j = 0; j < 32; ++j) {
            long long v = p[j];
            if (v < 0 || v >= n) ok = 0;
        }
        g_is64 = ok;
    }
}

// ---------------- CSR build -------------------------------------------------
__global__ void hist_kernel(const void* __restrict__ ei, int e, int n) {
    int idx = blockIdx.x * blockDim.x + threadIdx.x;
    if (idx < e) {
        int d = edge_val(ei, (long long)e + idx);
        if (d >= 0 && d < n) atomicAdd(&g_deg[d], 1);
    }
}

__global__ void scanA_kernel(int n) {
    __shared__ int s[512];
    int t = threadIdx.x;
    int i = blockIdx.x * 512 + t;
    int v = (i < n) ? g_deg[i] : 0;
    s[t] = v;
    __syncthreads();
    #pragma unroll
    for (int off = 1; off < 512; off <<= 1) {
        int add = (t >= off) ? s[t - off] : 0;
        __syncthreads();
        s[t] += add;
        __syncthreads();
    }
    if (i < n) g_incl[i] = s[t];
    if (t == 511) g_part[blockIdx.x] = s[511];
}

__global__ void scanB_kernel(int nchunks) {
    __shared__ int s[128];
    int t = threadIdx.x;
    int v = (t < nchunks) ? g_part[t] : 0;
    s[t] = v;
    __syncthreads();
    #pragma unroll
    for (int off = 1; off < 128; off <<= 1) {
        int add = (t >= off) ? s[t - off] : 0;
        __syncthreads();
        s[t] += add;
        __syncthreads();
    }
    if (t < nchunks) g_cbase[t] = s[t] - v;   // exclusive
}

__global__ void scanC_kernel(int n) {
    int i = blockIdx.x * blockDim.x + threadIdx.x;
    if (i < n) g_offs[i + 1] = g_cbase[i >> 9] + g_incl[i];
}

__global__ void scatter_kernel(const void* __restrict__ ei, int e, int n) {
    int idx = blockIdx.x * blockDim.x + threadIdx.x;
    if (idx < e) {
        int d = edge_val(ei, (long long)e + idx);
        int s = edge_val(ei, idx);
        if (d >= 0 && d < n && s >= 0 && s < n) {
            int pos = g_offs[d] + atomicAdd(&g_cursor[d], 1);
            g_srcs[pos] = s;
        }
    }
}

// ---------------- conversion passes -------------------------------------------
__global__ void xconv_kernel(const float* __restrict__ x, int total) {
    int i = blockIdx.x * blockDim.x + threadIdx.x;
    if (i < total) g_xf[i] = __float2half_rn(x[i]);
}

// transpose + fp16 hi/lo split of all 8 weight matrices
__global__ void wsplit_kernel(const float* w0, const float* w1, const float* w2, const float* w3,
                              const float* w4, const float* w5, const float* w6, const float* w7) {
    int tid = blockIdx.x * blockDim.x + threadIdx.x;
    if (tid >= 262144) return;
    float v;
    int idx;
    if (tid < 131072) {
        int m = tid >> 15, r = tid & 32767;
        int n = r >> 7, k = r & 127;
        const float* W = (m == 0) ? w0 : (m == 1) ? w1 : (m == 2) ? w2 : w3;
        v = W[k * 256 + n];
        idx = m * 32768 + n * 128 + k;
    } else {
        int e = tid - 131072;
        int m = e >> 15, r = e & 32767;
        int n = r >> 8, k = r & 255;
        const float* W = (m == 0) ? w4 : (m == 1) ? w5 : (m == 2) ? w6 : w7;
        v = W[k * 128 + n];
        idx = 131072 + m * 32768 + n * 256 + k;
    }
    __half hi = __float2half_rn(v);
    g_wh[idx] = hi;
    g_wl[idx] = __float2half_rn(v - __half2float(hi));
}

// ---------------- mma.sync fp16 GEMM, 2-term, 2-stage cp.async ----------------
// C = A(fp16) @ (Wh + Wl)^T + bias. A[M,K], Wt[N,K]. fp32 accum.
#define BK 32
#define LDT 40
#define TILE_ELEMS (128 * LDT)
#define STAGE_ELEMS (3 * TILE_ELEMS)            // A, Bh, Bl
#define GEMM_SMEM_BYTES (2 * STAGE_ELEMS * 2)   // 61440 B

__global__ __launch_bounds__(256, 2)
void mma_gemm_kernel(const float* __restrict__ b0, const float* __restrict__ b1,
                     const float* __restrict__ b2, const float* __restrict__ b3,
                     int M, int K, int ntiles, int wt_base, int layer, int out_base)
{
    extern __shared__ __align__(16) __half sm[];

    int tid = threadIdx.x, wid = tid >> 5, lane = tid & 31;
    int mat = blockIdx.x / ntiles, nt0 = blockIdx.x % ntiles;
    int m0 = blockIdx.y * 128;
    int n0 = nt0 * 128;
    int Ntot = ntiles * 128;

    const __half* Af = layer ? g_hf : g_xf;
    const __half* Bh = g_wh + wt_base + mat * 32768;
    const __half* Bl = g_wl + wt_base + mat * 32768;
    const float* bias = (mat == 0) ? b0 : (mat == 1) ? b1 : (mat == 2) ? b2 : b3;
    int osel = out_base + mat;
    bool is_half = (osel == 1 || osel == 2 || osel == 5 || osel == 6);

    int warp_m = wid >> 1;
    int warp_n = wid & 1;

    float acc[2][8][4];
    #pragma unroll
    for (int i = 0; i < 2; ++i)
        #pragma unroll
        for (int j = 0; j < 8; ++j)
            #pragma unroll
            for (int q = 0; q < 4; ++q) acc[i][j][q] = 0.0f;

    uint32_t smu = smem_u32(sm);
    int nchunks = K / BK;

    // 1536 16B-chunks per stage: t=0 A, t=1 Bh, t=2 Bl
    auto issue = [&](int kc) {
        int kb = kc * BK;
        uint32_t sbase = smu + (uint32_t)(kc & 1) * (STAGE_ELEMS * 2);
        #pragma unroll
        for (int it = 0; it < 6; ++it) {
            int i = tid + it * 256;
            int t = i >> 9, w = i & 511;
            int row = w >> 2, c8 = (w & 3) * 8;
            uint32_t dst = sbase + (uint32_t)(t * TILE_ELEMS + row * LDT + c8) * 2;
            if (t == 0) {
                int r = m0 + row;
                const void* sp = (r < M) ? (const void*)(Af + (size_t)r * K + kb + c8)
                                         : (const void*)Af;
                cpasync16(dst, sp, (r < M) ? 16 : 0);
            } else {
                const __half* Bp = (t == 1) ? Bh : Bl;
                cpasync16(dst, Bp + (size_t)(n0 + row) * K + kb + c8, 16);
            }
        }
        asm volatile("cp.async.commit_group;" ::: "memory");
    };

    uint32_t a_row = warp_m * 32 + (lane & 15);
    uint32_t a_koff = (lane >> 4) * 8;
    uint32_t b_nrow = warp_n * 64 + (lane & 7) + ((lane >> 3) & 1) * 8;
    uint32_t b_koff = (lane >> 4) * 8;

    issue(0);

    for (int kc = 0; kc < nchunks; ++kc) {
        if (kc + 1 < nchunks) {
            issue(kc + 1);
            asm volatile("cp.async.wait_group 1;" ::: "memory");
        } else {
            asm volatile("cp.async.wait_group 0;" ::: "memory");
        }
        __syncthreads();

        uint32_t sbase = smu + (uint32_t)(kc & 1) * (STAGE_ELEMS * 2);
        uint32_t sA_u  = sbase;
        uint32_t sBh_u = sbase + TILE_ELEMS * 2;
        uint32_t sBl_u = sbase + 2 * TILE_ELEMS * 2;

        #pragma unroll
        for (int ks = 0; ks < BK / 16; ++ks) {
            uint32_t aF[2][4], bH[4][4], bL[4][4];
            #pragma unroll
            for (int mt = 0; mt < 2; ++mt) {
                uint32_t off = ((a_row + mt * 16) * LDT + ks * 16 + a_koff) * 2;
                ldsm4(aF[mt], sA_u + off);
            }
            #pragma unroll
            for (int nb = 0; nb < 4; ++nb) {
                uint32_t off = ((b_nrow + nb * 16) * LDT + ks * 16 + b_koff) * 2;
                ldsm4(bH[nb], sBh_u + off);
                ldsm4(bL[nb], sBl_u + off);
            }
            #pragma unroll
            for (int mt = 0; mt < 2; ++mt) {
                #pragma unroll
                for (int j = 0; j < 8; ++j) {
                    int nb = j >> 1, par = j & 1;
                    mma_f16(acc[mt][j], aF[mt], bH[nb][par], bH[nb][par + 2]);
                    mma_f16(acc[mt][j], aF[mt], bL[nb][par], bL[nb][par + 2]);
                }
            }
        }
        __syncthreads();
    }

    if (is_half) {
        __half* Ch = buf_f16(osel);
        #pragma unroll
        for (int mt = 0; mt < 2; ++mt) {
            int r0 = m0 + warp_m * 32 + mt * 16 + (lane >> 2);
            #pragma unroll
            for (int j = 0; j < 8; ++j) {
                int c = n0 + warp_n * 64 + j * 8 + (lane & 3) * 2;
                float2 bv = *(const float2*)(bias + c);
                if (r0 < M) {
                    __half2 o0 = __floats2half2_rn(acc[mt][j][0] + bv.x,
                                                   acc[mt][j][1] + bv.y);
                    *(__half2*)(Ch + (size_t)r0 * Ntot + c) = o0;
                }
                if (r0 + 8 < M) {
                    __half2 o1 = __floats2half2_rn(acc[mt][j][2] + bv.x,
                                                   acc[mt][j][3] + bv.y);
                    *(__half2*)(Ch + (size_t)(r0 + 8) * Ntot + c) = o1;
                }
            }
        }
    } else {
        float* C = buf_f32(osel);
        #pragma unroll
        for (int mt = 0; mt < 2; ++mt) {
            int r0 = m0 + warp_m * 32 + mt * 16 + (lane >> 2);
            #pragma unroll
            for (int j = 0; j < 8; ++j) {
                int c = n0 + warp_n * 64 + j * 8 + (lane & 3) * 2;
                float2 bv = *(const float2*)(bias + c);
                if (r0 < M) {
                    float2 o0 = make_float2(acc[mt][j][0] + bv.x, acc[mt][j][1] + bv.y);
                    *(float2*)(C + (size_t)r0 * Ntot + c) = o0;
                }
                if (r0 + 8 < M) {
                    float2 o1 = make_float2(acc[mt][j][2] + bv.x, acc[mt][j][3] + bv.y);
                    *(float2*)(C + (size_t)(r0 + 8) * Ntot + c) = o1;
                }
            }
        }
    }
}

// unpack 8 halves (uint4) -> 8 floats
__device__ __forceinline__ void h8_to_f8(uint4 u, float* f) {
    union { uint4 u; __half2 h[4]; } c;
    c.u = u;
    #pragma unroll
    for (int j = 0; j < 4; ++j) {
        float2 p = __half22float2(c.h[j]);
        f[2 * j] = p.x;
        f[2 * j + 1] = p.y;
    }
}

// ---------------- attention layer 1 (fused skip+attn+relu+fp16 conv) ---------
__global__ void attn1_kernel(int n)
{
    int node = (blockIdx.x * blockDim.x + threadIdx.x) >> 5;
    int lane = threadIdx.x & 31;
    if (node >= n) return;

    int off = (lane >> 3) * 64 + (lane & 7) * 8;
    const float* qb = g_q1 + (size_t)node * D1 + off;
    float4 q0 = *(const float4*)qb;
    float4 q1 = *(const float4*)(qb + 4);
    float qf[8] = { q0.x, q0.y, q0.z, q0.w, q1.x, q1.y, q1.z, q1.w };

    float m = -1e30f, l = 0.0f;
    float A[8] = { 0.f, 0.f, 0.f, 0.f, 0.f, 0.f, 0.f, 0.f };

    int beg = g_offs[node], end = g_offs[node + 1];
    int p = beg;
    for (; p + 4 <= end; p += 4) {
        uint4 kr[4], vr[4];
        #pragma unroll
        for (int j = 0; j < 4; ++j) {
            int s = g_srcs[p + j];
            kr[j] = *(const uint4*)(g_k1h + (size_t)s * D1 + off);
            vr[j] = *(const uint4*)(g_v1h + (size_t)s * D1 + off);
        }
        float d[4];
        #pragma unroll
        for (int j = 0; j < 4; ++j) {
            float kf[8];
            h8_to_f8(kr[j], kf);
            float t = 0.f;
            #pragma unroll
            for (int q = 0; q < 8; ++q) t += qf[q] * kf[q];
            d[j] = t;
        }
        #pragma unroll
        for (int o = 4; o; o >>= 1)
            #pragma unroll
            for (int j = 0; j < 4; ++j)
                d[j] += __shfl_xor_sync(0xffffffffu, d[j], o);
        #pragma unroll
        for (int j = 0; j < 4; ++j) {
            float logit = d[j] * 0.125f;
            float mn = fmaxf(m, logit);
            float c = __expf(m - mn), pe = __expf(logit - mn);
            l = l * c + pe;
            float vf[8];
            h8_to_f8(vr[j], vf);
            #pragma unroll
            for (int q = 0; q < 8; ++q) A[q] = A[q] * c + pe * vf[q];
            m = mn;
        }
    }
    for (; p < end; ++p) {
        int s = g_srcs[p];
        uint4 kr = *(const uint4*)(g_k1h + (size_t)s * D1 + off);
        uint4 vr = *(const uint4*)(g_v1h + (size_t)s * D1 + off);
        float kf[8];
        h8_to_f8(kr, kf);
        float d0 = 0.f;
        #pragma unroll
        for (int q = 0; q < 8; ++q) d0 += qf[q] * kf[q];
        #pragma unroll
        for (int o = 4; o; o >>= 1) d0 += __shfl_xor_sync(0xffffffffu, d0, o);
        float logit = d0 * 0.125f;
        float mn = fmaxf(m, logit);
        float c = __expf(m - mn), pe = __expf(logit - mn);
        l = l * c + pe;
        float vf[8];
        h8_to_f8(vr, vf);
        #pragma unroll
        for (int q = 0; q < 8; ++q) A[q] = A[q] * c + pe * vf[q];
        m = mn;
    }

    float inv = (l > 0.0f) ? 1.0f / l : 0.0f;
    const float* hb = g_h + (size_t)node * D1 + off;
    float4 h0 = *(const float4*)hb;
    float4 h1 = *(const float4*)(hb + 4);
    float hv[8] = { h0.x, h0.y, h0.z, h0.w, h1.x, h1.y, h1.z, h1.w };

    union { uint4 u; __half2 h[4]; } hu;
    #pragma unroll
    for (int j = 0; j < 4; ++j) {
        float v0 = fmaxf(hv[2 * j]     + A[2 * j]     * inv, 0.0f);
        float v1 = fmaxf(hv[2 * j + 1] + A[2 * j + 1] * inv, 0.0f);
        hu.h[j] = __floats2half2_rn(v0, v1);
    }
    *(uint4*)(g_hf + (size_t)node * D1 + off) = hu.u;
}

// ---------------- attention layer 2: 1 head, d=128, warp per node, unroll 4 --
__global__ void attn2_kernel(int n)
{
    int node = (blockIdx.x * blockDim.x + threadIdx.x) >> 5;
    int lane = threadIdx.x & 31;
    if (node >= n) return;

    int base = node * EMB + 4 * lane;
    float4 qv = *(const float4*)(g_q2 + base);

    float m = -1e30f, l = 0.0f;
    float4 A = make_float4(0.f, 0.f, 0.f, 0.f);
    int beg = g_offs[node], end = g_offs[node + 1];
    const float scale = 0.088388347648318447f;   // 1/sqrt(128)

    int p = beg;
    for (; p + 4 <= end; p += 4) {
        uint2 kr[4], vr[4];
        #pragma unroll
        for (int j = 0; j < 4; ++j) {
            int s = g_srcs[p + j];
            kr[j] = *(const uint2*)(g_k2h + (size_t)s * EMB + 4 * lane);
            vr[j] = *(const uint2*)(g_v2h + (size_t)s * EMB + 4 * lane);
        }
        float d[4];
        #pragma unroll
        for (int j = 0; j < 4; ++j) {
            union { uint2 u; __half2 h[2]; } c;
            c.u = kr[j];
            float2 p0 = __half22float2(c.h[0]);
            float2 p1 = __half22float2(c.h[1]);
            d[j] = qv.x * p0.x + qv.y * p0.y + qv.z * p1.x + qv.w * p1.y;
        }
        #pragma unroll
        for (int o = 16; o; o >>= 1)
            #pragma unroll
            for (int j = 0; j < 4; ++j)
                d[j] += __shfl_xor_sync(0xffffffffu, d[j], o);
        #pragma unroll
        for (int j = 0; j < 4; ++j) {
            float logit = d[j] * scale;
            float mn = fmaxf(m, logit);
            float c = __expf(m - mn), pe = __expf(logit - mn);
            l = l * c + pe;
            union { uint2 u; __half2 h[2]; } cv;
            cv.u = vr[j];
            float2 v0 = __half22float2(cv.h[0]);
            float2 v1 = __half22float2(cv.h[1]);
            A.x = A.x * c + pe * v0.x; A.y = A.y * c + pe * v0.y;
            A.z = A.z * c + pe * v1.x; A.w = A.w * c + pe * v1.y;
            m = mn;
        }
    }
    for (; p < end; ++p) {
        int s = g_srcs[p];
        union { uint2 u; __half2 h[2]; } ck, cv;
        ck.u = *(const uint2*)(g_k2h + (size_t)s * EMB + 4 * lane);
        cv.u = *(const uint2*)(g_v2h + (size_t)s * EMB + 4 * lane);
        float2 p0 = __half22float2(ck.h[0]);
        float2 p1 = __half22float2(ck.h[1]);
        float d0 = qv.x * p0.x + qv.y * p0.y + qv.z * p1.x + qv.w * p1.y;
        #pragma unroll
        for (int o = 16; o; o >>= 1) d0 += __shfl_xor_sync(0xffffffffu, d0, o);
        float logit = d0 * scale;
        float mn = fmaxf(m, logit);
        float c = __expf(m - mn), pe = __expf(logit - mn);
        l = l * c + pe;
        float2 v0 = __half22float2(cv.h[0]);
        float2 v1 = __half22float2(cv.h[1]);
        A.x = A.x * c + pe * v0.x; A.y = A.y * c + pe * v0.y;
        A.z = A.z * c + pe * v1.x; A.w = A.w * c + pe * v1.y;
        m = mn;
    }
    if (l > 0.0f) {
        float inv = 1.0f / l;
        float4 o = *(float4*)(g_o2 + base);
        o.x += A.x * inv; o.y += A.y * inv; o.z += A.z * inv; o.w += A.w * inv;
        *(float4*)(g_o2 + base) = o;
    }
}

// ---------------- final mean over nodes (reads g_o2) -------------------------
__global__ void reduce_mean_kernel(float* __restrict__ out, int n) {
    int col = threadIdx.x;   // 128 threads
    float s = 0.0f;
    for (int r = blockIdx.x; r < n; r += gridDim.x)
        s += g_o2[(size_t)r * EMB + col];
    atomicAdd(&out[col], s * (1.0f / (float)n));
}

// ---------------- launch -----------------------------------------------------
extern "C" void kernel_launch(void* const* d_in, const int* in_sizes, int n_in,
                              void* d_out, int out_size)
{
    const float* x  = (const float*)d_in[0];
    const void*  ei = d_in[1];
    const float *Wq1 = (const float*)d_in[2],  *bq1 = (const float*)d_in[3];
    const float *Wk1 = (const float*)d_in[4],  *bk1 = (const float*)d_in[5];
    const float *Wv1 = (const float*)d_in[6],  *bv1 = (const float*)d_in[7];
    const float *Ws1 = (const float*)d_in[8],  *bs1 = (const float*)d_in[9];
    const float *Wq2 = (const float*)d_in[10], *bq2 = (const float*)d_in[11];
    const float *Wk2 = (const float*)d_in[12], *bk2 = (const float*)d_in[13];
    const float *Wv2 = (const float*)d_in[14], *bv2 = (const float*)d_in[15];
    const float *Ws2 = (const float*)d_in[16], *bs2 = (const float*)d_in[17];
    float* out = (float*)d_out;

    const int n = in_sizes[0] / INC;   // 50000
    const int e = in_sizes[1] / 2;     // 800000

    cudaFuncSetAttribute(mma_gemm_kernel,
                         cudaFuncAttributeMaxDynamicSharedMemorySize, GEMM_SMEM_BYTES);

    // ---- init (+dtype detect) + CSR build (by dst) ----
    {
        int threads = 256;
        init_kernel<<<(n + threads - 1) / threads, threads>>>(ei, out, n);
        hist_kernel<<<(e + threads - 1) / threads, threads>>>(ei, e, n);
        int nchunks = (n + 511) / 512;
        scanA_kernel<<<nchunks, 512>>>(n);
        scanB_kernel<<<1, 128>>>(nchunks);
        scanC_kernel<<<(n + threads - 1) / threads, threads>>>(n);
        scatter_kernel<<<(e + threads - 1) / threads, threads>>>(ei, e, n);
    }

    // ---- input conversions ----
    {
        int totx = n * INC;
        xconv_kernel<<<(totx + 255) / 256, 256>>>(x, totx);
        wsplit_kernel<<<1024, 256>>>(Wq1, Wk1, Wv1, Ws1, Wq2, Wk2, Wv2, Ws2);
    }

    int mtiles = (n + 127) / 128;

    // ---- layer 1 projections (q1 fp32, k1/v1 fp16, h fp32) ----
    {
        dim3 grid(8, mtiles);
        mma_gemm_kernel<<<grid, 256, GEMM_SMEM_BYTES>>>(bq1, bk1, bv1, bs1,
                                                        n, INC, 2, 0, 0, 0);
    }

    // ---- layer 1 attention (fused skip+attn+relu -> g_hf fp16) ----
    {
        int blocks = (n + 7) / 8;
        attn1_kernel<<<blocks, 256>>>(n);
    }

    // ---- layer 2 projections (q2 fp32, k2/v2 fp16, o2 fp32) ----
    {
        dim3 grid(4, mtiles);
        mma_gemm_kernel<<<grid, 256, GEMM_SMEM_BYTES>>>(bq2, bk2, bv2, bs2,
                                                        n, D1, 1, 131072, 1, 4);
    }

    // ---- layer 2 attention (adds into g_o2) ----
    {
        int blocks = (n + 7) / 8;
        attn2_kernel<<<blocks, 256>>>(n);
    }

    // ---- final mean over nodes ----
    reduce_mean_kernel<<<256, EMB>>>(out, n);
}